// round 13
// baseline (speedup 1.0000x reference)
#include <cuda_runtime.h>
#include <math.h>

// ---------------- problem constants ----------------
#define BB   2
#define TT_  2048
#define CC   1024
#define HH   16
#define HD_  64
#define FF_  2048
#define MR   4096                 // B*T rows
#define EPSV 1.1920928955078125e-07f   // float32 finfo eps

// ---------------- static scratch (no allocs allowed) ----------------
__device__ float g_x   [(size_t)MR * CC];   // rmsnorm1 output
__device__ float g_q   [(size_t)MR * CC];   // [b,t,h,d]
__device__ float g_k   [(size_t)MR * CC];
__device__ float g_v   [(size_t)MR * CC];
__device__ float g_attn[(size_t)MR * CC];   // [b,t,h,d] attention out
__device__ float g_t2  [(size_t)MR * CC];   // target + attn residual
__device__ float g_y   [(size_t)MR * CC];   // rmsnorm2 output
__device__ float g_h   [(size_t)MR * FF_];  // gelu(ffn1)
__device__ float g_S   [134217728ULL];      // [B,H,T,T] scores/probs (512 MB)

// ---------------- block reductions ----------------
__device__ __forceinline__ float block_reduce_sum(float v) {
    __shared__ float sh[33];
    int lane = threadIdx.x & 31, w = threadIdx.x >> 5;
    #pragma unroll
    for (int o = 16; o > 0; o >>= 1) v += __shfl_xor_sync(0xffffffffu, v, o);
    if (lane == 0) sh[w] = v;
    __syncthreads();
    if (threadIdx.x < 8) {
        float x = sh[threadIdx.x];
        #pragma unroll
        for (int o = 4; o > 0; o >>= 1) x += __shfl_xor_sync(0x000000ffu, x, o);
        if (threadIdx.x == 0) sh[32] = x;
    }
    __syncthreads();
    float r = sh[32];
    __syncthreads();
    return r;
}

__device__ __forceinline__ float block_reduce_max(float v) {
    __shared__ float sh[33];
    int lane = threadIdx.x & 31, w = threadIdx.x >> 5;
    #pragma unroll
    for (int o = 16; o > 0; o >>= 1) v = fmaxf(v, __shfl_xor_sync(0xffffffffu, v, o));
    if (lane == 0) sh[w] = v;
    __syncthreads();
    if (threadIdx.x < 8) {
        float x = sh[threadIdx.x];
        #pragma unroll
        for (int o = 4; o > 0; o >>= 1) x = fmaxf(x, __shfl_xor_sync(0x000000ffu, x, o));
        if (threadIdx.x == 0) sh[32] = x;
    }
    __syncthreads();
    float r = sh[32];
    __syncthreads();
    return r;
}

// ---------------- RMSNorm ----------------
__global__ void __launch_bounds__(256)
rmsnorm_k(const float* __restrict__ in, const float* __restrict__ g,
          float* __restrict__ out) {
    const int row = blockIdx.x;
    const float* xp = in + (size_t)row * CC;
    float ss = 0.f;
    for (int i = threadIdx.x; i < CC; i += 256) { float v = xp[i]; ss = fmaf(v, v, ss); }
    ss = block_reduce_sum(ss);
    const float inv = rsqrtf(ss * (1.0f / CC) + EPSV);
    float* yp = out + (size_t)row * CC;
    for (int i = threadIdx.x; i < CC; i += 256) yp[i] = xp[i] * inv * g[i];
}

// ---------------- generic tiled SGEMM:  C[M,N] = A[M,K] @ B[N,K]^T (+epilogue) ----
// EPI: 0 = none, 1 = +bias, 2 = +bias+resid, 3 = gelu_exact(+bias)
// 64x64 block tile, BK=16, 256 threads, 4x4 register tile per thread.
template<int EPI>
__global__ void __launch_bounds__(256)
gemm_bt(const float* __restrict__ A, const float* __restrict__ Bm,
        const float* __restrict__ bias, const float* __restrict__ resid,
        float* __restrict__ Cm, int M, int N, int K) {
    __shared__ float As[16][68];
    __shared__ float Bs[16][68];
    const int tid = threadIdx.x;
    const int tx = tid & 15, ty = tid >> 4;
    const int m0 = blockIdx.y * 64;
    const int n0 = blockIdx.x * 64;
    const int lr = tid >> 2;          // 0..63
    const int lc = (tid & 3) * 4;     // 0,4,8,12
    const float* Ap = A  + (size_t)(m0 + lr) * K + lc;
    const float* Bp = Bm + (size_t)(n0 + lr) * K + lc;
    float acc[4][4] = {};
    for (int k0 = 0; k0 < K; k0 += 16) {
        float4 a = *(const float4*)(Ap + k0);
        float4 b = *(const float4*)(Bp + k0);
        As[lc + 0][lr] = a.x; As[lc + 1][lr] = a.y; As[lc + 2][lr] = a.z; As[lc + 3][lr] = a.w;
        Bs[lc + 0][lr] = b.x; Bs[lc + 1][lr] = b.y; Bs[lc + 2][lr] = b.z; Bs[lc + 3][lr] = b.w;
        __syncthreads();
        #pragma unroll
        for (int kk = 0; kk < 16; kk++) {
            float4 av = *(const float4*)&As[kk][ty * 4];
            float4 bv = *(const float4*)&Bs[kk][tx * 4];
            float ar[4] = {av.x, av.y, av.z, av.w};
            float br[4] = {bv.x, bv.y, bv.z, bv.w};
            #pragma unroll
            for (int i = 0; i < 4; i++)
                #pragma unroll
                for (int j = 0; j < 4; j++)
                    acc[i][j] = fmaf(ar[i], br[j], acc[i][j]);
        }
        __syncthreads();
    }
    #pragma unroll
    for (int i = 0; i < 4; i++) {
        const int row = m0 + ty * 4 + i;
        const int col = n0 + tx * 4;
        float4 out;
        float* o = &out.x;
        #pragma unroll
        for (int j = 0; j < 4; j++) {
            float v = acc[i][j];
            if (EPI >= 1) v += bias[col + j];
            if (EPI == 2) v += resid[(size_t)row * N + col + j];
            if (EPI == 3) v = 0.5f * v * (1.0f + erff(v * 0.70710678118654752f));
            o[j] = v;
        }
        *(float4*)&Cm[(size_t)row * N + col] = out;
    }
}

// ---------------- attention scores: S = scale * Q @ K^T (causal tiles only) ----
__global__ void __launch_bounds__(256)
attn_scores_k() {
    const int st = blockIdx.x, tt = blockIdx.y, bh = blockIdx.z;
    if (st > tt) return;                    // fully masked tile
    const int b = bh >> 4, h = bh & 15;
    const int tid = threadIdx.x;
    const int tx = tid & 15, ty = tid >> 4;
    const int t0 = tt * 64, s0 = st * 64;
    const float* Qp = g_q + (size_t)b * TT_ * CC + h * HD_;
    const float* Kp = g_k + (size_t)b * TT_ * CC + h * HD_;
    __shared__ float As[16][68];
    __shared__ float Bs[16][68];
    const int lr = tid >> 2, lc = (tid & 3) * 4;
    float acc[4][4] = {};
    for (int k0 = 0; k0 < HD_; k0 += 16) {
        float4 a = *(const float4*)(Qp + (size_t)(t0 + lr) * CC + k0 + lc);
        float4 b4 = *(const float4*)(Kp + (size_t)(s0 + lr) * CC + k0 + lc);
        As[lc + 0][lr] = a.x;  As[lc + 1][lr] = a.y;  As[lc + 2][lr] = a.z;  As[lc + 3][lr] = a.w;
        Bs[lc + 0][lr] = b4.x; Bs[lc + 1][lr] = b4.y; Bs[lc + 2][lr] = b4.z; Bs[lc + 3][lr] = b4.w;
        __syncthreads();
        #pragma unroll
        for (int kk = 0; kk < 16; kk++) {
            float4 av = *(const float4*)&As[kk][ty * 4];
            float4 bv = *(const float4*)&Bs[kk][tx * 4];
            float ar[4] = {av.x, av.y, av.z, av.w};
            float br[4] = {bv.x, bv.y, bv.z, bv.w};
            #pragma unroll
            for (int i = 0; i < 4; i++)
                #pragma unroll
                for (int j = 0; j < 4; j++)
                    acc[i][j] = fmaf(ar[i], br[j], acc[i][j]);
        }
        __syncthreads();
    }
    float* Sp = g_S + (size_t)bh * TT_ * TT_;
    #pragma unroll
    for (int i = 0; i < 4; i++) {
        const int row = t0 + ty * 4 + i;
        const int col = s0 + tx * 4;
        float4 out;
        out.x = acc[i][0] * 0.125f;
        out.y = acc[i][1] * 0.125f;
        out.z = acc[i][2] * 0.125f;
        out.w = acc[i][3] * 0.125f;
        *(float4*)&Sp[(size_t)row * TT_ + col] = out;
    }
}

// ---------------- causal row softmax (only reads s<=t; zeroes tile pad) -------
__global__ void __launch_bounds__(256)
softmax_k() {
    const int rid = blockIdx.x;            // (b*H+h)*T + t
    const int t = rid & (TT_ - 1);
    float* p = g_S + (size_t)rid * TT_;
    const int n = t + 1;
    float m = -3.4e38f;
    for (int i = threadIdx.x; i < n; i += 256) m = fmaxf(m, p[i]);
    m = block_reduce_max(m);
    float s = 0.f;
    for (int i = threadIdx.x; i < n; i += 256) {
        float e = __expf(p[i] - m);
        p[i] = e;
        s += e;
    }
    s = block_reduce_sum(s);
    const float inv = 1.0f / s;
    for (int i = threadIdx.x; i < n; i += 256) p[i] *= inv;
    const int pad = (t | 63) + 1;          // zero up to 64-aligned tile end
    for (int i = n + threadIdx.x; i < pad; i += 256) p[i] = 0.f;
}

// ---------------- attn = P @ V  (causal K-extent per q-tile) ------------------
__global__ void __launch_bounds__(256)
attn_av_k() {
    const int tt = blockIdx.x, bh = blockIdx.y;
    const int b = bh >> 4, h = bh & 15;
    const int t0 = tt * 64;
    const int tid = threadIdx.x;
    const int tx = tid & 15, ty = tid >> 4;
    const float* Sp = g_S + (size_t)bh * TT_ * TT_ + (size_t)t0 * TT_;
    const float* Vp = g_v + (size_t)b * TT_ * CC + h * HD_;
    __shared__ float As[16][68];           // P tile transposed [k][m]
    __shared__ float Bs[16][68];           // V tile [k][n]
    const int lr = tid >> 2, lc = (tid & 3) * 4;
    const int kk2 = tid >> 4, cc = (tid & 15) * 4;
    float acc[4][4] = {};
    const int nk = (tt + 1) * 64;
    for (int k0 = 0; k0 < nk; k0 += 16) {
        float4 a = *(const float4*)(Sp + (size_t)lr * TT_ + k0 + lc);
        As[lc + 0][lr] = a.x; As[lc + 1][lr] = a.y; As[lc + 2][lr] = a.z; As[lc + 3][lr] = a.w;
        float4 bv = *(const float4*)(Vp + (size_t)(k0 + kk2) * CC + cc);
        *(float4*)&Bs[kk2][cc] = bv;
        __syncthreads();
        #pragma unroll
        for (int kk = 0; kk < 16; kk++) {
            float4 av = *(const float4*)&As[kk][ty * 4];
            float4 bw = *(const float4*)&Bs[kk][tx * 4];
            float ar[4] = {av.x, av.y, av.z, av.w};
            float br[4] = {bw.x, bw.y, bw.z, bw.w};
            #pragma unroll
            for (int i = 0; i < 4; i++)
                #pragma unroll
                for (int j = 0; j < 4; j++)
                    acc[i][j] = fmaf(ar[i], br[j], acc[i][j]);
        }
        __syncthreads();
    }
    #pragma unroll
    for (int i = 0; i < 4; i++) {
        const int row = t0 + ty * 4 + i;
        float4 out;
        out.x = acc[i][0]; out.y = acc[i][1]; out.z = acc[i][2]; out.w = acc[i][3];
        *(float4*)&g_attn[(size_t)(b * TT_ + row) * CC + h * HD_ + tx * 4] = out;
    }
}

// ---------------- launch -------------------------------------------------------
extern "C" void kernel_launch(void* const* d_in, const int* in_sizes, int n_in,
                              void* d_out, int out_size) {
    const float* target = (const float*)d_in[0];
    const float* wq     = (const float*)d_in[1];   // [H,HD,C] == [C,C]
    const float* wk     = (const float*)d_in[2];
    const float* wv     = (const float*)d_in[3];
    const float* w_proj = (const float*)d_in[4];   // [C, C]
    const float* b_proj = (const float*)d_in[5];
    const float* w1     = (const float*)d_in[6];   // [FF, C]
    const float* b1     = (const float*)d_in[7];
    const float* w2     = (const float*)d_in[8];   // [C, FF]
    const float* b2     = (const float*)d_in[9];
    const float* g1     = (const float*)d_in[10];
    const float* g2     = (const float*)d_in[11];
    float* out = (float*)d_out;

    float *px, *pq, *pk, *pv, *pattn, *pt2, *py, *ph;
    cudaGetSymbolAddress((void**)&px,    g_x);
    cudaGetSymbolAddress((void**)&pq,    g_q);
    cudaGetSymbolAddress((void**)&pk,    g_k);
    cudaGetSymbolAddress((void**)&pv,    g_v);
    cudaGetSymbolAddress((void**)&pattn, g_attn);
    cudaGetSymbolAddress((void**)&pt2,   g_t2);
    cudaGetSymbolAddress((void**)&py,    g_y);
    cudaGetSymbolAddress((void**)&ph,    g_h);

    const dim3 gC (CC  / 64, MR / 64);   // (16, 64)
    const dim3 gFF(FF_ / 64, MR / 64);   // (32, 64)

    // x = rmsnorm(target, g1)
    rmsnorm_k<<<MR, 256>>>(target, g1, px);
    // q,k,v projections (output layout [b,t,h,d] == [M, C])
    gemm_bt<0><<<gC, 256>>>(px, wq, nullptr, nullptr, pq, MR, CC, CC);
    gemm_bt<0><<<gC, 256>>>(px, wk, nullptr, nullptr, pk, MR, CC, CC);
    gemm_bt<0><<<gC, 256>>>(px, wv, nullptr, nullptr, pv, MR, CC, CC);
    // S = scale * Q K^T (lower-triangle tiles only)
    attn_scores_k<<<dim3(TT_ / 64, TT_ / 64, BB * HH), 256>>>();
    // causal softmax rows
    softmax_k<<<BB * HH * TT_, 256>>>();
    // attn = P @ V
    attn_av_k<<<dim3(TT_ / 64, BB * HH), 256>>>();
    // t2 = target + attn @ Wp^T + bp
    gemm_bt<2><<<gC, 256>>>(pattn, w_proj, b_proj, target, pt2, MR, CC, CC);
    // y = rmsnorm(t2, g2)
    rmsnorm_k<<<MR, 256>>>(pt2, g2, py);
    // h = gelu(y @ W1^T + b1)
    gemm_bt<3><<<gFF, 256>>>(py, w1, b1, nullptr, ph, MR, FF_, CC);
    // out = t2 + h @ W2^T + b2
    gemm_bt<2><<<gC, 256>>>(ph, w2, b2, pt2, out, MR, CC, FF_);
}

// round 14
// speedup vs baseline: 1.6225x; 1.6225x over previous
#include <cuda_runtime.h>
#include <math.h>

// ---------------- problem constants ----------------
#define BB   2
#define TT_  2048
#define CC   1024
#define HH   16
#define HD_  64
#define FF_  2048
#define MR   4096                 // B*T rows
#define EPSV 1.1920928955078125e-07f   // float32 finfo eps

// ---------------- static scratch (no allocs allowed) ----------------
__device__ float g_x   [(size_t)MR * CC];   // rmsnorm1 output
__device__ float g_q   [(size_t)MR * CC];   // [b,t,h,d]
__device__ float g_k   [(size_t)MR * CC];
__device__ float g_v   [(size_t)MR * CC];
__device__ float g_attn[(size_t)MR * CC];   // [b,t,h,d] attention out
__device__ float g_t2  [(size_t)MR * CC];   // target + attn residual
__device__ float g_y   [(size_t)MR * CC];   // rmsnorm2 output
__device__ float g_h   [(size_t)MR * FF_];  // gelu(ffn1)
__device__ float g_S   [134217728ULL];      // [B,H,T,T] scores/probs (512 MB)

// ---------------- block reductions ----------------
__device__ __forceinline__ float block_reduce_sum(float v) {
    __shared__ float sh[33];
    int lane = threadIdx.x & 31, w = threadIdx.x >> 5;
    #pragma unroll
    for (int o = 16; o > 0; o >>= 1) v += __shfl_xor_sync(0xffffffffu, v, o);
    if (lane == 0) sh[w] = v;
    __syncthreads();
    if (threadIdx.x < 8) {
        float x = sh[threadIdx.x];
        #pragma unroll
        for (int o = 4; o > 0; o >>= 1) x += __shfl_xor_sync(0x000000ffu, x, o);
        if (threadIdx.x == 0) sh[32] = x;
    }
    __syncthreads();
    float r = sh[32];
    __syncthreads();
    return r;
}

__device__ __forceinline__ float block_reduce_max(float v) {
    __shared__ float sh[33];
    int lane = threadIdx.x & 31, w = threadIdx.x >> 5;
    #pragma unroll
    for (int o = 16; o > 0; o >>= 1) v = fmaxf(v, __shfl_xor_sync(0xffffffffu, v, o));
    if (lane == 0) sh[w] = v;
    __syncthreads();
    if (threadIdx.x < 8) {
        float x = sh[threadIdx.x];
        #pragma unroll
        for (int o = 4; o > 0; o >>= 1) x = fmaxf(x, __shfl_xor_sync(0x000000ffu, x, o));
        if (threadIdx.x == 0) sh[32] = x;
    }
    __syncthreads();
    float r = sh[32];
    __syncthreads();
    return r;
}

// ---------------- RMSNorm ----------------
__global__ void __launch_bounds__(256)
rmsnorm_k(const float* __restrict__ in, const float* __restrict__ g,
          float* __restrict__ out) {
    const int row = blockIdx.x;
    const float* xp = in + (size_t)row * CC;
    float ss = 0.f;
    for (int i = threadIdx.x; i < CC; i += 256) { float v = xp[i]; ss = fmaf(v, v, ss); }
    ss = block_reduce_sum(ss);
    const float inv = rsqrtf(ss * (1.0f / CC) + EPSV);
    float* yp = out + (size_t)row * CC;
    for (int i = threadIdx.x; i < CC; i += 256) yp[i] = xp[i] * inv * g[i];
}

// ---------------- generic tiled SGEMM:  C[M,N] = A[M,K] @ B[N,K]^T (+epilogue) ----
// EPI: 0 = none, 1 = +bias, 2 = +bias+resid, 3 = gelu_exact(+bias)
// 64x64 block tile, BK=16, 256 threads, 4x4 register tile per thread.
template<int EPI>
__global__ void __launch_bounds__(256)
gemm_bt(const float* __restrict__ A, const float* __restrict__ Bm,
        const float* __restrict__ bias, const float* __restrict__ resid,
        float* __restrict__ Cm, int M, int N, int K) {
    __shared__ float As[16][68];
    __shared__ float Bs[16][68];
    const int tid = threadIdx.x;
    const int tx = tid & 15, ty = tid >> 4;
    const int m0 = blockIdx.y * 64;
    const int n0 = blockIdx.x * 64;
    const int lr = tid >> 2;          // 0..63
    const int lc = (tid & 3) * 4;     // 0,4,8,12
    const float* Ap = A  + (size_t)(m0 + lr) * K + lc;
    const float* Bp = Bm + (size_t)(n0 + lr) * K + lc;
    float acc[4][4] = {};
    for (int k0 = 0; k0 < K; k0 += 16) {
        float4 a = *(const float4*)(Ap + k0);
        float4 b = *(const float4*)(Bp + k0);
        As[lc + 0][lr] = a.x; As[lc + 1][lr] = a.y; As[lc + 2][lr] = a.z; As[lc + 3][lr] = a.w;
        Bs[lc + 0][lr] = b.x; Bs[lc + 1][lr] = b.y; Bs[lc + 2][lr] = b.z; Bs[lc + 3][lr] = b.w;
        __syncthreads();
        #pragma unroll
        for (int kk = 0; kk < 16; kk++) {
            float4 av = *(const float4*)&As[kk][ty * 4];
            float4 bv = *(const float4*)&Bs[kk][tx * 4];
            float ar[4] = {av.x, av.y, av.z, av.w};
            float br[4] = {bv.x, bv.y, bv.z, bv.w};
            #pragma unroll
            for (int i = 0; i < 4; i++)
                #pragma unroll
                for (int j = 0; j < 4; j++)
                    acc[i][j] = fmaf(ar[i], br[j], acc[i][j]);
        }
        __syncthreads();
    }
    #pragma unroll
    for (int i = 0; i < 4; i++) {
        const int row = m0 + ty * 4 + i;
        const int col = n0 + tx * 4;
        float4 out;
        float* o = &out.x;
        #pragma unroll
        for (int j = 0; j < 4; j++) {
            float v = acc[i][j];
            if (EPI >= 1) v += bias[col + j];
            if (EPI == 2) v += resid[(size_t)row * N + col + j];
            if (EPI == 3) v = 0.5f * v * (1.0f + erff(v * 0.70710678118654752f));
            o[j] = v;
        }
        *(float4*)&Cm[(size_t)row * N + col] = out;
    }
}

// ---------------- attention scores: S = scale * Q @ K^T (causal tiles only) ----
__global__ void __launch_bounds__(256)
attn_scores_k() {
    const int st = blockIdx.x, tt = blockIdx.y, bh = blockIdx.z;
    if (st > tt) return;                    // fully masked tile
    const int b = bh >> 4, h = bh & 15;
    const int tid = threadIdx.x;
    const int tx = tid & 15, ty = tid >> 4;
    const int t0 = tt * 64, s0 = st * 64;
    const float* Qp = g_q + (size_t)b * TT_ * CC + h * HD_;
    const float* Kp = g_k + (size_t)b * TT_ * CC + h * HD_;
    __shared__ float As[16][68];
    __shared__ float Bs[16][68];
    const int lr = tid >> 2, lc = (tid & 3) * 4;
    float acc[4][4] = {};
    for (int k0 = 0; k0 < HD_; k0 += 16) {
        float4 a = *(const float4*)(Qp + (size_t)(t0 + lr) * CC + k0 + lc);
        float4 b4 = *(const float4*)(Kp + (size_t)(s0 + lr) * CC + k0 + lc);
        As[lc + 0][lr] = a.x;  As[lc + 1][lr] = a.y;  As[lc + 2][lr] = a.z;  As[lc + 3][lr] = a.w;
        Bs[lc + 0][lr] = b4.x; Bs[lc + 1][lr] = b4.y; Bs[lc + 2][lr] = b4.z; Bs[lc + 3][lr] = b4.w;
        __syncthreads();
        #pragma unroll
        for (int kk = 0; kk < 16; kk++) {
            float4 av = *(const float4*)&As[kk][ty * 4];
            float4 bv = *(const float4*)&Bs[kk][tx * 4];
            float ar[4] = {av.x, av.y, av.z, av.w};
            float br[4] = {bv.x, bv.y, bv.z, bv.w};
            #pragma unroll
            for (int i = 0; i < 4; i++)
                #pragma unroll
                for (int j = 0; j < 4; j++)
                    acc[i][j] = fmaf(ar[i], br[j], acc[i][j]);
        }
        __syncthreads();
    }
    float* Sp = g_S + (size_t)bh * TT_ * TT_;
    #pragma unroll
    for (int i = 0; i < 4; i++) {
        const int row = t0 + ty * 4 + i;
        const int col = s0 + tx * 4;
        float4 out;
        out.x = acc[i][0] * 0.125f;
        out.y = acc[i][1] * 0.125f;
        out.z = acc[i][2] * 0.125f;
        out.w = acc[i][3] * 0.125f;
        *(float4*)&Sp[(size_t)row * TT_ + col] = out;
    }
}

// ---------------- causal row softmax (only reads s<=t; zeroes tile pad) -------
__global__ void __launch_bounds__(256)
softmax_k() {
    const int rid = blockIdx.x;            // (b*H+h)*T + t
    const int t = rid & (TT_ - 1);
    float* p = g_S + (size_t)rid * TT_;
    const int n = t + 1;
    float m = -3.4e38f;
    for (int i = threadIdx.x; i < n; i += 256) m = fmaxf(m, p[i]);
    m = block_reduce_max(m);
    float s = 0.f;
    for (int i = threadIdx.x; i < n; i += 256) {
        float e = __expf(p[i] - m);
        p[i] = e;
        s += e;
    }
    s = block_reduce_sum(s);
    const float inv = 1.0f / s;
    for (int i = threadIdx.x; i < n; i += 256) p[i] *= inv;
    const int pad = (t | 63) + 1;          // zero up to 64-aligned tile end
    for (int i = n + threadIdx.x; i < pad; i += 256) p[i] = 0.f;
}

// ---------------- attn = P @ V  (causal K-extent per q-tile) ------------------
__global__ void __launch_bounds__(256)
attn_av_k() {
    const int tt = blockIdx.x, bh = blockIdx.y;
    const int b = bh >> 4, h = bh & 15;
    const int t0 = tt * 64;
    const int tid = threadIdx.x;
    const int tx = tid & 15, ty = tid >> 4;
    const float* Sp = g_S + (size_t)bh * TT_ * TT_ + (size_t)t0 * TT_;
    const float* Vp = g_v + (size_t)b * TT_ * CC + h * HD_;
    __shared__ float As[16][68];           // P tile transposed [k][m]
    __shared__ float Bs[16][68];           // V tile [k][n]
    const int lr = tid >> 2, lc = (tid & 3) * 4;
    const int kk2 = tid >> 4, cc = (tid & 15) * 4;
    float acc[4][4] = {};
    const int nk = (tt + 1) * 64;
    for (int k0 = 0; k0 < nk; k0 += 16) {
        float4 a = *(const float4*)(Sp + (size_t)lr * TT_ + k0 + lc);
        As[lc + 0][lr] = a.x; As[lc + 1][lr] = a.y; As[lc + 2][lr] = a.z; As[lc + 3][lr] = a.w;
        float4 bv = *(const float4*)(Vp + (size_t)(k0 + kk2) * CC + cc);
        *(float4*)&Bs[kk2][cc] = bv;
        __syncthreads();
        #pragma unroll
        for (int kk = 0; kk < 16; kk++) {
            float4 av = *(const float4*)&As[kk][ty * 4];
            float4 bw = *(const float4*)&Bs[kk][tx * 4];
            float ar[4] = {av.x, av.y, av.z, av.w};
            float br[4] = {bw.x, bw.y, bw.z, bw.w};
            #pragma unroll
            for (int i = 0; i < 4; i++)
                #pragma unroll
                for (int j = 0; j < 4; j++)
                    acc[i][j] = fmaf(ar[i], br[j], acc[i][j]);
        }
        __syncthreads();
    }
    #pragma unroll
    for (int i = 0; i < 4; i++) {
        const int row = t0 + ty * 4 + i;
        float4 out;
        out.x = acc[i][0]; out.y = acc[i][1]; out.z = acc[i][2]; out.w = acc[i][3];
        *(float4*)&g_attn[(size_t)(b * TT_ + row) * CC + h * HD_ + tx * 4] = out;
    }
}

// ---------------- launch -------------------------------------------------------
extern "C" void kernel_launch(void* const* d_in, const int* in_sizes, int n_in,
                              void* d_out, int out_size) {
    const float* target = (const float*)d_in[0];
    const float* wq     = (const float*)d_in[1];   // [H,HD,C] == [C,C]
    const float* wk     = (const float*)d_in[2];
    const float* wv     = (const float*)d_in[3];
    const float* w_proj = (const float*)d_in[4];   // [C, C]
    const float* b_proj = (const float*)d_in[5];
    const float* w1     = (const float*)d_in[6];   // [FF, C]
    const float* b1     = (const float*)d_in[7];
    const float* w2     = (const float*)d_in[8];   // [C, FF]
    const float* b2     = (const float*)d_in[9];
    const float* g1     = (const float*)d_in[10];
    const float* g2     = (const float*)d_in[11];
    float* out = (float*)d_out;

    float *px, *pq, *pk, *pv, *pattn, *pt2, *py, *ph;
    cudaGetSymbolAddress((void**)&px,    g_x);
    cudaGetSymbolAddress((void**)&pq,    g_q);
    cudaGetSymbolAddress((void**)&pk,    g_k);
    cudaGetSymbolAddress((void**)&pv,    g_v);
    cudaGetSymbolAddress((void**)&pattn, g_attn);
    cudaGetSymbolAddress((void**)&pt2,   g_t2);
    cudaGetSymbolAddress((void**)&py,    g_y);
    cudaGetSymbolAddress((void**)&ph,    g_h);

    const dim3 gC (CC  / 64, MR / 64);   // (16, 64)
    const dim3 gFF(FF_ / 64, MR / 64);   // (32, 64)

    // x = rmsnorm(target, g1)
    rmsnorm_k<<<MR, 256>>>(target, g1, px);
    // q,k,v projections (output layout [b,t,h,d] == [M, C])
    gemm_bt<0><<<gC, 256>>>(px, wq, nullptr, nullptr, pq, MR, CC, CC);
    gemm_bt<0><<<gC, 256>>>(px, wk, nullptr, nullptr, pk, MR, CC, CC);
    gemm_bt<0><<<gC, 256>>>(px, wv, nullptr, nullptr, pv, MR, CC, CC);
    // S = scale * Q K^T (lower-triangle tiles only)
    attn_scores_k<<<dim3(TT_ / 64, TT_ / 64, BB * HH), 256>>>();
    // causal softmax rows
    softmax_k<<<BB * HH * TT_, 256>>>();
    // attn = P @ V
    attn_av_k<<<dim3(TT_ / 64, BB * HH), 256>>>();
    // t2 = target + attn @ Wp^T + bp
    gemm_bt<2><<<gC, 256>>>(pattn, w_proj, b_proj, target, pt2, MR, CC, CC);
    // y = rmsnorm(t2, g2)
    rmsnorm_k<<<MR, 256>>>(pt2, g2, py);
    // h = gelu(y @ W1^T + b1)
    gemm_bt<3><<<gFF, 256>>>(py, w1, b1, nullptr, ph, MR, FF_, CC);
    // out = t2 + h @ W2^T + b2
    gemm_bt<2><<<gC, 256>>>(ph, w2, b2, pt2, out, MR, CC, FF_);
}

// round 15
// speedup vs baseline: 1.6236x; 1.0006x over previous
#include <cuda_runtime.h>
#include <math.h>

// ---------------- problem constants ----------------
#define BB   2
#define TT_  2048
#define CC   1024
#define HH   16
#define HD_  64
#define FF_  2048
#define MR   4096                 // B*T rows
#define EPSV 1.1920928955078125e-07f   // float32 finfo eps

// ---------------- static scratch (no allocs allowed) ----------------
__device__ float g_x   [(size_t)MR * CC];   // rmsnorm1 output
__device__ float g_q   [(size_t)MR * CC];   // [b,t,h,d]
__device__ float g_k   [(size_t)MR * CC];
__device__ float g_v   [(size_t)MR * CC];
__device__ float g_attn[(size_t)MR * CC];   // [b,t,h,d] attention out
__device__ float g_t2  [(size_t)MR * CC];   // target + attn residual
__device__ float g_y   [(size_t)MR * CC];   // rmsnorm2 output
__device__ float g_h   [(size_t)MR * FF_];  // gelu(ffn1)
__device__ float g_S   [134217728ULL];      // [B,H,T,T] scores/probs (512 MB)

// ---------------- block reductions ----------------
__device__ __forceinline__ float block_reduce_sum(float v) {
    __shared__ float sh[33];
    int lane = threadIdx.x & 31, w = threadIdx.x >> 5;
    #pragma unroll
    for (int o = 16; o > 0; o >>= 1) v += __shfl_xor_sync(0xffffffffu, v, o);
    if (lane == 0) sh[w] = v;
    __syncthreads();
    if (threadIdx.x < 8) {
        float x = sh[threadIdx.x];
        #pragma unroll
        for (int o = 4; o > 0; o >>= 1) x += __shfl_xor_sync(0x000000ffu, x, o);
        if (threadIdx.x == 0) sh[32] = x;
    }
    __syncthreads();
    float r = sh[32];
    __syncthreads();
    return r;
}

__device__ __forceinline__ float block_reduce_max(float v) {
    __shared__ float sh[33];
    int lane = threadIdx.x & 31, w = threadIdx.x >> 5;
    #pragma unroll
    for (int o = 16; o > 0; o >>= 1) v = fmaxf(v, __shfl_xor_sync(0xffffffffu, v, o));
    if (lane == 0) sh[w] = v;
    __syncthreads();
    if (threadIdx.x < 8) {
        float x = sh[threadIdx.x];
        #pragma unroll
        for (int o = 4; o > 0; o >>= 1) x = fmaxf(x, __shfl_xor_sync(0x000000ffu, x, o));
        if (threadIdx.x == 0) sh[32] = x;
    }
    __syncthreads();
    float r = sh[32];
    __syncthreads();
    return r;
}

// ---------------- RMSNorm ----------------
__global__ void __launch_bounds__(256)
rmsnorm_k(const float* __restrict__ in, const float* __restrict__ g,
          float* __restrict__ out) {
    const int row = blockIdx.x;
    const float* xp = in + (size_t)row * CC;
    float ss = 0.f;
    for (int i = threadIdx.x; i < CC; i += 256) { float v = xp[i]; ss = fmaf(v, v, ss); }
    ss = block_reduce_sum(ss);
    const float inv = rsqrtf(ss * (1.0f / CC) + EPSV);
    float* yp = out + (size_t)row * CC;
    for (int i = threadIdx.x; i < CC; i += 256) yp[i] = xp[i] * inv * g[i];
}

// ---------------- generic tiled SGEMM:  C[M,N] = A[M,K] @ B[N,K]^T (+epilogue) ----
// EPI: 0 = none, 1 = +bias, 2 = +bias+resid, 3 = gelu_exact(+bias)
// 64x64 block tile, BK=16, 256 threads, 4x4 register tile per thread.
template<int EPI>
__global__ void __launch_bounds__(256)
gemm_bt(const float* __restrict__ A, const float* __restrict__ Bm,
        const float* __restrict__ bias, const float* __restrict__ resid,
        float* __restrict__ Cm, int M, int N, int K) {
    __shared__ float As[16][68];
    __shared__ float Bs[16][68];
    const int tid = threadIdx.x;
    const int tx = tid & 15, ty = tid >> 4;
    const int m0 = blockIdx.y * 64;
    const int n0 = blockIdx.x * 64;
    const int lr = tid >> 2;          // 0..63
    const int lc = (tid & 3) * 4;     // 0,4,8,12
    const float* Ap = A  + (size_t)(m0 + lr) * K + lc;
    const float* Bp = Bm + (size_t)(n0 + lr) * K + lc;
    float acc[4][4] = {};
    for (int k0 = 0; k0 < K; k0 += 16) {
        float4 a = *(const float4*)(Ap + k0);
        float4 b = *(const float4*)(Bp + k0);
        As[lc + 0][lr] = a.x; As[lc + 1][lr] = a.y; As[lc + 2][lr] = a.z; As[lc + 3][lr] = a.w;
        Bs[lc + 0][lr] = b.x; Bs[lc + 1][lr] = b.y; Bs[lc + 2][lr] = b.z; Bs[lc + 3][lr] = b.w;
        __syncthreads();
        #pragma unroll
        for (int kk = 0; kk < 16; kk++) {
            float4 av = *(const float4*)&As[kk][ty * 4];
            float4 bv = *(const float4*)&Bs[kk][tx * 4];
            float ar[4] = {av.x, av.y, av.z, av.w};
            float br[4] = {bv.x, bv.y, bv.z, bv.w};
            #pragma unroll
            for (int i = 0; i < 4; i++)
                #pragma unroll
                for (int j = 0; j < 4; j++)
                    acc[i][j] = fmaf(ar[i], br[j], acc[i][j]);
        }
        __syncthreads();
    }
    #pragma unroll
    for (int i = 0; i < 4; i++) {
        const int row = m0 + ty * 4 + i;
        const int col = n0 + tx * 4;
        float4 out;
        float* o = &out.x;
        #pragma unroll
        for (int j = 0; j < 4; j++) {
            float v = acc[i][j];
            if (EPI >= 1) v += bias[col + j];
            if (EPI == 2) v += resid[(size_t)row * N + col + j];
            if (EPI == 3) v = 0.5f * v * (1.0f + erff(v * 0.70710678118654752f));
            o[j] = v;
        }
        *(float4*)&Cm[(size_t)row * N + col] = out;
    }
}

// ---------------- attention scores: S = scale * Q @ K^T (causal tiles only) ----
__global__ void __launch_bounds__(256)
attn_scores_k() {
    const int st = blockIdx.x, tt = blockIdx.y, bh = blockIdx.z;
    if (st > tt) return;                    // fully masked tile
    const int b = bh >> 4, h = bh & 15;
    const int tid = threadIdx.x;
    const int tx = tid & 15, ty = tid >> 4;
    const int t0 = tt * 64, s0 = st * 64;
    const float* Qp = g_q + (size_t)b * TT_ * CC + h * HD_;
    const float* Kp = g_k + (size_t)b * TT_ * CC + h * HD_;
    __shared__ float As[16][68];
    __shared__ float Bs[16][68];
    const int lr = tid >> 2, lc = (tid & 3) * 4;
    float acc[4][4] = {};
    for (int k0 = 0; k0 < HD_; k0 += 16) {
        float4 a = *(const float4*)(Qp + (size_t)(t0 + lr) * CC + k0 + lc);
        float4 b4 = *(const float4*)(Kp + (size_t)(s0 + lr) * CC + k0 + lc);
        As[lc + 0][lr] = a.x;  As[lc + 1][lr] = a.y;  As[lc + 2][lr] = a.z;  As[lc + 3][lr] = a.w;
        Bs[lc + 0][lr] = b4.x; Bs[lc + 1][lr] = b4.y; Bs[lc + 2][lr] = b4.z; Bs[lc + 3][lr] = b4.w;
        __syncthreads();
        #pragma unroll
        for (int kk = 0; kk < 16; kk++) {
            float4 av = *(const float4*)&As[kk][ty * 4];
            float4 bv = *(const float4*)&Bs[kk][tx * 4];
            float ar[4] = {av.x, av.y, av.z, av.w};
            float br[4] = {bv.x, bv.y, bv.z, bv.w};
            #pragma unroll
            for (int i = 0; i < 4; i++)
                #pragma unroll
                for (int j = 0; j < 4; j++)
                    acc[i][j] = fmaf(ar[i], br[j], acc[i][j]);
        }
        __syncthreads();
    }
    float* Sp = g_S + (size_t)bh * TT_ * TT_;
    #pragma unroll
    for (int i = 0; i < 4; i++) {
        const int row = t0 + ty * 4 + i;
        const int col = s0 + tx * 4;
        float4 out;
        out.x = acc[i][0] * 0.125f;
        out.y = acc[i][1] * 0.125f;
        out.z = acc[i][2] * 0.125f;
        out.w = acc[i][3] * 0.125f;
        *(float4*)&Sp[(size_t)row * TT_ + col] = out;
    }
}

// ---------------- causal row softmax (only reads s<=t; zeroes tile pad) -------
__global__ void __launch_bounds__(256)
softmax_k() {
    const int rid = blockIdx.x;            // (b*H+h)*T + t
    const int t = rid & (TT_ - 1);
    float* p = g_S + (size_t)rid * TT_;
    const int n = t + 1;
    float m = -3.4e38f;
    for (int i = threadIdx.x; i < n; i += 256) m = fmaxf(m, p[i]);
    m = block_reduce_max(m);
    float s = 0.f;
    for (int i = threadIdx.x; i < n; i += 256) {
        float e = __expf(p[i] - m);
        p[i] = e;
        s += e;
    }
    s = block_reduce_sum(s);
    const float inv = 1.0f / s;
    for (int i = threadIdx.x; i < n; i += 256) p[i] *= inv;
    const int pad = (t | 63) + 1;          // zero up to 64-aligned tile end
    for (int i = n + threadIdx.x; i < pad; i += 256) p[i] = 0.f;
}

// ---------------- attn = P @ V  (causal K-extent per q-tile) ------------------
__global__ void __launch_bounds__(256)
attn_av_k() {
    const int tt = blockIdx.x, bh = blockIdx.y;
    const int b = bh >> 4, h = bh & 15;
    const int t0 = tt * 64;
    const int tid = threadIdx.x;
    const int tx = tid & 15, ty = tid >> 4;
    const float* Sp = g_S + (size_t)bh * TT_ * TT_ + (size_t)t0 * TT_;
    const float* Vp = g_v + (size_t)b * TT_ * CC + h * HD_;
    __shared__ float As[16][68];           // P tile transposed [k][m]
    __shared__ float Bs[16][68];           // V tile [k][n]
    const int lr = tid >> 2, lc = (tid & 3) * 4;
    const int kk2 = tid >> 4, cc = (tid & 15) * 4;
    float acc[4][4] = {};
    const int nk = (tt + 1) * 64;
    for (int k0 = 0; k0 < nk; k0 += 16) {
        float4 a = *(const float4*)(Sp + (size_t)lr * TT_ + k0 + lc);
        As[lc + 0][lr] = a.x; As[lc + 1][lr] = a.y; As[lc + 2][lr] = a.z; As[lc + 3][lr] = a.w;
        float4 bv = *(const float4*)(Vp + (size_t)(k0 + kk2) * CC + cc);
        *(float4*)&Bs[kk2][cc] = bv;
        __syncthreads();
        #pragma unroll
        for (int kk = 0; kk < 16; kk++) {
            float4 av = *(const float4*)&As[kk][ty * 4];
            float4 bw = *(const float4*)&Bs[kk][tx * 4];
            float ar[4] = {av.x, av.y, av.z, av.w};
            float br[4] = {bw.x, bw.y, bw.z, bw.w};
            #pragma unroll
            for (int i = 0; i < 4; i++)
                #pragma unroll
                for (int j = 0; j < 4; j++)
                    acc[i][j] = fmaf(ar[i], br[j], acc[i][j]);
        }
        __syncthreads();
    }
    #pragma unroll
    for (int i = 0; i < 4; i++) {
        const int row = t0 + ty * 4 + i;
        float4 out;
        out.x = acc[i][0]; out.y = acc[i][1]; out.z = acc[i][2]; out.w = acc[i][3];
        *(float4*)&g_attn[(size_t)(b * TT_ + row) * CC + h * HD_ + tx * 4] = out;
    }
}

// ---------------- launch -------------------------------------------------------
extern "C" void kernel_launch(void* const* d_in, const int* in_sizes, int n_in,
                              void* d_out, int out_size) {
    const float* target = (const float*)d_in[0];
    const float* wq     = (const float*)d_in[1];   // [H,HD,C] == [C,C]
    const float* wk     = (const float*)d_in[2];
    const float* wv     = (const float*)d_in[3];
    const float* w_proj = (const float*)d_in[4];   // [C, C]
    const float* b_proj = (const float*)d_in[5];
    const float* w1     = (const float*)d_in[6];   // [FF, C]
    const float* b1     = (const float*)d_in[7];
    const float* w2     = (const float*)d_in[8];   // [C, FF]
    const float* b2     = (const float*)d_in[9];
    const float* g1     = (const float*)d_in[10];
    const float* g2     = (const float*)d_in[11];
    float* out = (float*)d_out;

    float *px, *pq, *pk, *pv, *pattn, *pt2, *py, *ph;
    cudaGetSymbolAddress((void**)&px,    g_x);
    cudaGetSymbolAddress((void**)&pq,    g_q);
    cudaGetSymbolAddress((void**)&pk,    g_k);
    cudaGetSymbolAddress((void**)&pv,    g_v);
    cudaGetSymbolAddress((void**)&pattn, g_attn);
    cudaGetSymbolAddress((void**)&pt2,   g_t2);
    cudaGetSymbolAddress((void**)&py,    g_y);
    cudaGetSymbolAddress((void**)&ph,    g_h);

    const dim3 gC (CC  / 64, MR / 64);   // (16, 64)
    const dim3 gFF(FF_ / 64, MR / 64);   // (32, 64)

    // x = rmsnorm(target, g1)
    rmsnorm_k<<<MR, 256>>>(target, g1, px);
    // q,k,v projections (output layout [b,t,h,d] == [M, C])
    gemm_bt<0><<<gC, 256>>>(px, wq, nullptr, nullptr, pq, MR, CC, CC);
    gemm_bt<0><<<gC, 256>>>(px, wk, nullptr, nullptr, pk, MR, CC, CC);
    gemm_bt<0><<<gC, 256>>>(px, wv, nullptr, nullptr, pv, MR, CC, CC);
    // S = scale * Q K^T (lower-triangle tiles only)
    attn_scores_k<<<dim3(TT_ / 64, TT_ / 64, BB * HH), 256>>>();
    // causal softmax rows
    softmax_k<<<BB * HH * TT_, 256>>>();
    // attn = P @ V
    attn_av_k<<<dim3(TT_ / 64, BB * HH), 256>>>();
    // t2 = target + attn @ Wp^T + bp
    gemm_bt<2><<<gC, 256>>>(pattn, w_proj, b_proj, target, pt2, MR, CC, CC);
    // y = rmsnorm(t2, g2)
    rmsnorm_k<<<MR, 256>>>(pt2, g2, py);
    // h = gelu(y @ W1^T + b1)
    gemm_bt<3><<<gFF, 256>>>(py, w1, b1, nullptr, ph, MR, FF_, CC);
    // out = t2 + h @ W2^T + b2
    gemm_bt<2><<<gC, 256>>>(ph, w2, b2, pt2, out, MR, CC, FF_);
}

// round 16
// speedup vs baseline: 1.6245x; 1.0006x over previous
#include <cuda_runtime.h>
#include <math.h>

// ---------------- problem constants ----------------
#define BB   2
#define TT_  2048
#define CC   1024
#define HH   16
#define HD_  64
#define FF_  2048
#define MR   4096                 // B*T rows
#define EPSV 1.1920928955078125e-07f   // float32 finfo eps

// ---------------- static scratch (no allocs allowed) ----------------
__device__ float g_x   [(size_t)MR * CC];   // rmsnorm1 output
__device__ float g_q   [(size_t)MR * CC];   // [b,t,h,d]
__device__ float g_k   [(size_t)MR * CC];
__device__ float g_v   [(size_t)MR * CC];
__device__ float g_attn[(size_t)MR * CC];   // [b,t,h,d] attention out
__device__ float g_t2  [(size_t)MR * CC];   // target + attn residual
__device__ float g_y   [(size_t)MR * CC];   // rmsnorm2 output
__device__ float g_h   [(size_t)MR * FF_];  // gelu(ffn1)
__device__ float g_S   [134217728ULL];      // [B,H,T,T] scores/probs (512 MB)

// ---------------- block reductions ----------------
__device__ __forceinline__ float block_reduce_sum(float v) {
    __shared__ float sh[33];
    int lane = threadIdx.x & 31, w = threadIdx.x >> 5;
    #pragma unroll
    for (int o = 16; o > 0; o >>= 1) v += __shfl_xor_sync(0xffffffffu, v, o);
    if (lane == 0) sh[w] = v;
    __syncthreads();
    if (threadIdx.x < 8) {
        float x = sh[threadIdx.x];
        #pragma unroll
        for (int o = 4; o > 0; o >>= 1) x += __shfl_xor_sync(0x000000ffu, x, o);
        if (threadIdx.x == 0) sh[32] = x;
    }
    __syncthreads();
    float r = sh[32];
    __syncthreads();
    return r;
}

__device__ __forceinline__ float block_reduce_max(float v) {
    __shared__ float sh[33];
    int lane = threadIdx.x & 31, w = threadIdx.x >> 5;
    #pragma unroll
    for (int o = 16; o > 0; o >>= 1) v = fmaxf(v, __shfl_xor_sync(0xffffffffu, v, o));
    if (lane == 0) sh[w] = v;
    __syncthreads();
    if (threadIdx.x < 8) {
        float x = sh[threadIdx.x];
        #pragma unroll
        for (int o = 4; o > 0; o >>= 1) x = fmaxf(x, __shfl_xor_sync(0x000000ffu, x, o));
        if (threadIdx.x == 0) sh[32] = x;
    }
    __syncthreads();
    float r = sh[32];
    __syncthreads();
    return r;
}

// ---------------- RMSNorm ----------------
__global__ void __launch_bounds__(256)
rmsnorm_k(const float* __restrict__ in, const float* __restrict__ g,
          float* __restrict__ out) {
    const int row = blockIdx.x;
    const float* xp = in + (size_t)row * CC;
    float ss = 0.f;
    for (int i = threadIdx.x; i < CC; i += 256) { float v = xp[i]; ss = fmaf(v, v, ss); }
    ss = block_reduce_sum(ss);
    const float inv = rsqrtf(ss * (1.0f / CC) + EPSV);
    float* yp = out + (size_t)row * CC;
    for (int i = threadIdx.x; i < CC; i += 256) yp[i] = xp[i] * inv * g[i];
}

// ---------------- generic tiled SGEMM:  C[M,N] = A[M,K] @ B[N,K]^T (+epilogue) ----
// EPI: 0 = none, 1 = +bias, 2 = +bias+resid, 3 = gelu_exact(+bias)
// 64x64 block tile, BK=16, 256 threads, 4x4 register tile per thread.
template<int EPI>
__global__ void __launch_bounds__(256)
gemm_bt(const float* __restrict__ A, const float* __restrict__ Bm,
        const float* __restrict__ bias, const float* __restrict__ resid,
        float* __restrict__ Cm, int M, int N, int K) {
    __shared__ float As[16][68];
    __shared__ float Bs[16][68];
    const int tid = threadIdx.x;
    const int tx = tid & 15, ty = tid >> 4;
    const int m0 = blockIdx.y * 64;
    const int n0 = blockIdx.x * 64;
    const int lr = tid >> 2;          // 0..63
    const int lc = (tid & 3) * 4;     // 0,4,8,12
    const float* Ap = A  + (size_t)(m0 + lr) * K + lc;
    const float* Bp = Bm + (size_t)(n0 + lr) * K + lc;
    float acc[4][4] = {};
    for (int k0 = 0; k0 < K; k0 += 16) {
        float4 a = *(const float4*)(Ap + k0);
        float4 b = *(const float4*)(Bp + k0);
        As[lc + 0][lr] = a.x; As[lc + 1][lr] = a.y; As[lc + 2][lr] = a.z; As[lc + 3][lr] = a.w;
        Bs[lc + 0][lr] = b.x; Bs[lc + 1][lr] = b.y; Bs[lc + 2][lr] = b.z; Bs[lc + 3][lr] = b.w;
        __syncthreads();
        #pragma unroll
        for (int kk = 0; kk < 16; kk++) {
            float4 av = *(const float4*)&As[kk][ty * 4];
            float4 bv = *(const float4*)&Bs[kk][tx * 4];
            float ar[4] = {av.x, av.y, av.z, av.w};
            float br[4] = {bv.x, bv.y, bv.z, bv.w};
            #pragma unroll
            for (int i = 0; i < 4; i++)
                #pragma unroll
                for (int j = 0; j < 4; j++)
                    acc[i][j] = fmaf(ar[i], br[j], acc[i][j]);
        }
        __syncthreads();
    }
    #pragma unroll
    for (int i = 0; i < 4; i++) {
        const int row = m0 + ty * 4 + i;
        const int col = n0 + tx * 4;
        float4 out;
        float* o = &out.x;
        #pragma unroll
        for (int j = 0; j < 4; j++) {
            float v = acc[i][j];
            if (EPI >= 1) v += bias[col + j];
            if (EPI == 2) v += resid[(size_t)row * N + col + j];
            if (EPI == 3) v = 0.5f * v * (1.0f + erff(v * 0.70710678118654752f));
            o[j] = v;
        }
        *(float4*)&Cm[(size_t)row * N + col] = out;
    }
}

// ---------------- attention scores: S = scale * Q @ K^T (causal tiles only) ----
__global__ void __launch_bounds__(256)
attn_scores_k() {
    const int st = blockIdx.x, tt = blockIdx.y, bh = blockIdx.z;
    if (st > tt) return;                    // fully masked tile
    const int b = bh >> 4, h = bh & 15;
    const int tid = threadIdx.x;
    const int tx = tid & 15, ty = tid >> 4;
    const int t0 = tt * 64, s0 = st * 64;
    const float* Qp = g_q + (size_t)b * TT_ * CC + h * HD_;
    const float* Kp = g_k + (size_t)b * TT_ * CC + h * HD_;
    __shared__ float As[16][68];
    __shared__ float Bs[16][68];
    const int lr = tid >> 2, lc = (tid & 3) * 4;
    float acc[4][4] = {};
    for (int k0 = 0; k0 < HD_; k0 += 16) {
        float4 a = *(const float4*)(Qp + (size_t)(t0 + lr) * CC + k0 + lc);
        float4 b4 = *(const float4*)(Kp + (size_t)(s0 + lr) * CC + k0 + lc);
        As[lc + 0][lr] = a.x;  As[lc + 1][lr] = a.y;  As[lc + 2][lr] = a.z;  As[lc + 3][lr] = a.w;
        Bs[lc + 0][lr] = b4.x; Bs[lc + 1][lr] = b4.y; Bs[lc + 2][lr] = b4.z; Bs[lc + 3][lr] = b4.w;
        __syncthreads();
        #pragma unroll
        for (int kk = 0; kk < 16; kk++) {
            float4 av = *(const float4*)&As[kk][ty * 4];
            float4 bv = *(const float4*)&Bs[kk][tx * 4];
            float ar[4] = {av.x, av.y, av.z, av.w};
            float br[4] = {bv.x, bv.y, bv.z, bv.w};
            #pragma unroll
            for (int i = 0; i < 4; i++)
                #pragma unroll
                for (int j = 0; j < 4; j++)
                    acc[i][j] = fmaf(ar[i], br[j], acc[i][j]);
        }
        __syncthreads();
    }
    float* Sp = g_S + (size_t)bh * TT_ * TT_;
    #pragma unroll
    for (int i = 0; i < 4; i++) {
        const int row = t0 + ty * 4 + i;
        const int col = s0 + tx * 4;
        float4 out;
        out.x = acc[i][0] * 0.125f;
        out.y = acc[i][1] * 0.125f;
        out.z = acc[i][2] * 0.125f;
        out.w = acc[i][3] * 0.125f;
        *(float4*)&Sp[(size_t)row * TT_ + col] = out;
    }
}

// ---------------- causal row softmax (only reads s<=t; zeroes tile pad) -------
__global__ void __launch_bounds__(256)
softmax_k() {
    const int rid = blockIdx.x;            // (b*H+h)*T + t
    const int t = rid & (TT_ - 1);
    float* p = g_S + (size_t)rid * TT_;
    const int n = t + 1;
    float m = -3.4e38f;
    for (int i = threadIdx.x; i < n; i += 256) m = fmaxf(m, p[i]);
    m = block_reduce_max(m);
    float s = 0.f;
    for (int i = threadIdx.x; i < n; i += 256) {
        float e = __expf(p[i] - m);
        p[i] = e;
        s += e;
    }
    s = block_reduce_sum(s);
    const float inv = 1.0f / s;
    for (int i = threadIdx.x; i < n; i += 256) p[i] *= inv;
    const int pad = (t | 63) + 1;          // zero up to 64-aligned tile end
    for (int i = n + threadIdx.x; i < pad; i += 256) p[i] = 0.f;
}

// ---------------- attn = P @ V  (causal K-extent per q-tile) ------------------
__global__ void __launch_bounds__(256)
attn_av_k() {
    const int tt = blockIdx.x, bh = blockIdx.y;
    const int b = bh >> 4, h = bh & 15;
    const int t0 = tt * 64;
    const int tid = threadIdx.x;
    const int tx = tid & 15, ty = tid >> 4;
    const float* Sp = g_S + (size_t)bh * TT_ * TT_ + (size_t)t0 * TT_;
    const float* Vp = g_v + (size_t)b * TT_ * CC + h * HD_;
    __shared__ float As[16][68];           // P tile transposed [k][m]
    __shared__ float Bs[16][68];           // V tile [k][n]
    const int lr = tid >> 2, lc = (tid & 3) * 4;
    const int kk2 = tid >> 4, cc = (tid & 15) * 4;
    float acc[4][4] = {};
    const int nk = (tt + 1) * 64;
    for (int k0 = 0; k0 < nk; k0 += 16) {
        float4 a = *(const float4*)(Sp + (size_t)lr * TT_ + k0 + lc);
        As[lc + 0][lr] = a.x; As[lc + 1][lr] = a.y; As[lc + 2][lr] = a.z; As[lc + 3][lr] = a.w;
        float4 bv = *(const float4*)(Vp + (size_t)(k0 + kk2) * CC + cc);
        *(float4*)&Bs[kk2][cc] = bv;
        __syncthreads();
        #pragma unroll
        for (int kk = 0; kk < 16; kk++) {
            float4 av = *(const float4*)&As[kk][ty * 4];
            float4 bw = *(const float4*)&Bs[kk][tx * 4];
            float ar[4] = {av.x, av.y, av.z, av.w};
            float br[4] = {bw.x, bw.y, bw.z, bw.w};
            #pragma unroll
            for (int i = 0; i < 4; i++)
                #pragma unroll
                for (int j = 0; j < 4; j++)
                    acc[i][j] = fmaf(ar[i], br[j], acc[i][j]);
        }
        __syncthreads();
    }
    #pragma unroll
    for (int i = 0; i < 4; i++) {
        const int row = t0 + ty * 4 + i;
        float4 out;
        out.x = acc[i][0]; out.y = acc[i][1]; out.z = acc[i][2]; out.w = acc[i][3];
        *(float4*)&g_attn[(size_t)(b * TT_ + row) * CC + h * HD_ + tx * 4] = out;
    }
}

// ---------------- launch -------------------------------------------------------
extern "C" void kernel_launch(void* const* d_in, const int* in_sizes, int n_in,
                              void* d_out, int out_size) {
    const float* target = (const float*)d_in[0];
    const float* wq     = (const float*)d_in[1];   // [H,HD,C] == [C,C]
    const float* wk     = (const float*)d_in[2];
    const float* wv     = (const float*)d_in[3];
    const float* w_proj = (const float*)d_in[4];   // [C, C]
    const float* b_proj = (const float*)d_in[5];
    const float* w1     = (const float*)d_in[6];   // [FF, C]
    const float* b1     = (const float*)d_in[7];
    const float* w2     = (const float*)d_in[8];   // [C, FF]
    const float* b2     = (const float*)d_in[9];
    const float* g1     = (const float*)d_in[10];
    const float* g2     = (const float*)d_in[11];
    float* out = (float*)d_out;

    float *px, *pq, *pk, *pv, *pattn, *pt2, *py, *ph;
    cudaGetSymbolAddress((void**)&px,    g_x);
    cudaGetSymbolAddress((void**)&pq,    g_q);
    cudaGetSymbolAddress((void**)&pk,    g_k);
    cudaGetSymbolAddress((void**)&pv,    g_v);
    cudaGetSymbolAddress((void**)&pattn, g_attn);
    cudaGetSymbolAddress((void**)&pt2,   g_t2);
    cudaGetSymbolAddress((void**)&py,    g_y);
    cudaGetSymbolAddress((void**)&ph,    g_h);

    const dim3 gC (CC  / 64, MR / 64);   // (16, 64)
    const dim3 gFF(FF_ / 64, MR / 64);   // (32, 64)

    // x = rmsnorm(target, g1)
    rmsnorm_k<<<MR, 256>>>(target, g1, px);
    // q,k,v projections (output layout [b,t,h,d] == [M, C])
    gemm_bt<0><<<gC, 256>>>(px, wq, nullptr, nullptr, pq, MR, CC, CC);
    gemm_bt<0><<<gC, 256>>>(px, wk, nullptr, nullptr, pk, MR, CC, CC);
    gemm_bt<0><<<gC, 256>>>(px, wv, nullptr, nullptr, pv, MR, CC, CC);
    // S = scale * Q K^T (lower-triangle tiles only)
    attn_scores_k<<<dim3(TT_ / 64, TT_ / 64, BB * HH), 256>>>();
    // causal softmax rows
    softmax_k<<<BB * HH * TT_, 256>>>();
    // attn = P @ V
    attn_av_k<<<dim3(TT_ / 64, BB * HH), 256>>>();
    // t2 = target + attn @ Wp^T + bp
    gemm_bt<2><<<gC, 256>>>(pattn, w_proj, b_proj, target, pt2, MR, CC, CC);
    // y = rmsnorm(t2, g2)
    rmsnorm_k<<<MR, 256>>>(pt2, g2, py);
    // h = gelu(y @ W1^T + b1)
    gemm_bt<3><<<gFF, 256>>>(py, w1, b1, nullptr, ph, MR, FF_, CC);
    // out = t2 + h @ W2^T + b2
    gemm_bt<2><<<gC, 256>>>(ph, w2, b2, pt2, out, MR, CC, FF_);
}